// round 7
// baseline (speedup 1.0000x reference)
#include <cuda_runtime.h>
#include <cuda_bf16.h>
#include <stdint.h>

#define DINL static __device__ __forceinline__

namespace {
constexpr int Bn = 8;
constexpr int Cn = 128;
constexpr int Nn = 4096;
constexpr int BM = 128;     // query rows per CTA
constexpr int BN = 64;      // keys per iteration
constexpr int SOSTR = 133;  // fp32 epilogue smem stride (floats)
constexpr int KSTR = 136;   // proj smem stride (bf16 elems)
constexpr int QS = 144;     // flash q/k smem row stride (bytes, fp8)
constexpr int VS = 80;      // flash vT smem row stride (bytes, fp8)
}

// -------- scratch (no allocations allowed) --------
__device__ __align__(128) uint8_t g_q8[(size_t)Bn * Nn * Cn];   // fp8 q [b][n][d], x16
__device__ __align__(128) uint8_t g_k8[(size_t)Bn * Nn * Cn];   // fp8 k [b][n][d], x16
__device__ __align__(128) uint8_t g_vt[(size_t)Bn * Cn * Nn];   // fp8 v^T [b][d][perm(m)], x16
__device__ __align__(128) __nv_bfloat16 g_w2[3 * Cn * Cn];      // [p][o][k] = pw*dw*16 (bf16)

// ---------------- PTX helpers ----------------
DINL uint32_t smem_u32(const void* p) { return (uint32_t)__cvta_generic_to_shared(p); }

DINL void ldsm_x4(uint32_t& r0, uint32_t& r1, uint32_t& r2, uint32_t& r3, uint32_t a) {
    asm volatile("ldmatrix.sync.aligned.m8n8.x4.shared.b16 {%0,%1,%2,%3}, [%4];"
                 : "=r"(r0), "=r"(r1), "=r"(r2), "=r"(r3) : "r"(a));
}
DINL void ldsm_x4_t(uint32_t& r0, uint32_t& r1, uint32_t& r2, uint32_t& r3, uint32_t a) {
    asm volatile("ldmatrix.sync.aligned.m8n8.x4.trans.shared.b16 {%0,%1,%2,%3}, [%4];"
                 : "=r"(r0), "=r"(r1), "=r"(r2), "=r"(r3) : "r"(a));
}
DINL void ldsm_x2(uint32_t& r0, uint32_t& r1, uint32_t a) {
    asm volatile("ldmatrix.sync.aligned.m8n8.x2.shared.b16 {%0,%1}, [%2];"
                 : "=r"(r0), "=r"(r1) : "r"(a));
}
DINL void mma16816(float* c, uint32_t a0, uint32_t a1, uint32_t a2, uint32_t a3,
                   uint32_t b0, uint32_t b1) {
    asm volatile("mma.sync.aligned.m16n8k16.row.col.f32.bf16.bf16.f32 "
                 "{%0,%1,%2,%3}, {%4,%5,%6,%7}, {%8,%9}, {%0,%1,%2,%3};"
                 : "+f"(c[0]), "+f"(c[1]), "+f"(c[2]), "+f"(c[3])
                 : "r"(a0), "r"(a1), "r"(a2), "r"(a3), "r"(b0), "r"(b1));
}
DINL void mma16832(float* c, uint32_t a0, uint32_t a1, uint32_t a2, uint32_t a3,
                   uint32_t b0, uint32_t b1) {
    asm volatile("mma.sync.aligned.m16n8k32.row.col.f32.e4m3.e4m3.f32 "
                 "{%0,%1,%2,%3}, {%4,%5,%6,%7}, {%8,%9}, {%0,%1,%2,%3};"
                 : "+f"(c[0]), "+f"(c[1]), "+f"(c[2]), "+f"(c[3])
                 : "r"(a0), "r"(a1), "r"(a2), "r"(a3), "r"(b0), "r"(b1));
}
DINL uint32_t pack_bf16(float lo, float hi) {
    uint32_t r;
    asm("cvt.rn.bf16x2.f32 %0, %1, %2;" : "=r"(r) : "f"(hi), "f"(lo));
    return r;
}
DINL uint16_t e4m3x2(float lo, float hi) {
    uint16_t h;
    asm("cvt.rn.satfinite.e4m3x2.f32 %0, %1, %2;" : "=h"(h) : "f"(hi), "f"(lo));
    return h;
}
DINL uint8_t e4m3_1(float v) {
    uint16_t h;
    asm("cvt.rn.satfinite.e4m3x2.f32 %0, %1, %2;" : "=h"(h) : "f"(0.f), "f"(v));
    return (uint8_t)h;
}
DINL uint32_t e4m3x4(float s0, float s1, float s2, float s3) {
    uint32_t h01 = e4m3x2(s0, s1);
    uint32_t h23 = e4m3x2(s2, s3);
    return h01 | (h23 << 16);
}
DINL void cp_async16(uint32_t saddr, const void* gptr) {
    asm volatile("cp.async.cg.shared.global [%0], [%1], 16;" :: "r"(saddr), "l"(gptr));
}
DINL void cp_commit() { asm volatile("cp.async.commit_group;"); }
template <int N> DINL void cp_wait() { asm volatile("cp.async.wait_group %0;" :: "n"(N)); }

// key-group permutation inverse: column position for key (within 16)
DINL int finv8(int g) { return ((g >> 1) << 2) | (g & 1); }  // g in 0..7

// ---------------- kernel 1: fold dw (and fp8 scale 16) into pw ----------------
__global__ void prep_weights_kernel(const float* __restrict__ pwq, const float* __restrict__ dwq,
                                    const float* __restrict__ pwk, const float* __restrict__ dwk,
                                    const float* __restrict__ pwv, const float* __restrict__ dwv) {
    int idx = blockIdx.x * blockDim.x + threadIdx.x;
    if (idx >= 3 * Cn * Cn) return;
    int p = idx / (Cn * Cn);
    int r = idx - p * (Cn * Cn);
    int o = r / Cn;
    int k = r - o * Cn;
    const float* pw = (p == 0) ? pwq : (p == 1 ? pwk : pwv);
    const float* dw = (p == 0) ? dwq : (p == 1 ? dwk : dwv);
    g_w2[idx] = __float2bfloat16(pw[o * Cn + k] * dw[k] * 16.0f);
}

// ---------------- kernel 2: q/k/v projections on tensor cores, fp8 outputs --------
__global__ __launch_bounds__(256, 1)
void proj_kernel(const float* __restrict__ x) {
    extern __shared__ char smraw[];
    __nv_bfloat16* xs = (__nv_bfloat16*)smraw;     // [128 k][KSTR]
    __nv_bfloat16* ws = xs + Cn * KSTR;            // [3][128 o][KSTR]
    const int b   = blockIdx.y;
    const int n0  = blockIdx.x * 128;
    const int tid = threadIdx.x;
    const int wid = tid >> 5;
    const int lane = tid & 31;

#pragma unroll
    for (int i = 0; i < 24; i++) {
        int idx = tid + i * 256;
        int po  = idx >> 4;
        int c8  = (idx & 15) * 8;
        *(uint4*)&ws[po * KSTR + c8] = *(const uint4*)(g_w2 + (size_t)po * Cn + c8);
    }
    const float* xb = x + (size_t)b * Cn * Nn + n0;
#pragma unroll
    for (int i = 0; i < 16; i++) {
        int idx = tid + i * 256;
        int row = idx >> 5;
        int n4  = (idx & 31) * 4;
        float4 v = *(const float4*)(xb + (size_t)row * Nn + n4);
        uint32_t lo = pack_bf16(v.x, v.y);
        uint32_t hi = pack_bf16(v.z, v.w);
        *(uint2*)&xs[row * KSTR + n4] = make_uint2(lo, hi);
    }
    __syncthreads();

    const uint32_t xsa = smem_u32(xs);
    const uint32_t wsa = smem_u32(ws);
    const int a_krow = ((lane >> 4) & 1) * 8 + (lane & 7);
    const int a_ncol = ((lane >> 3) & 1) * 8;
    const uint32_t a_base = xsa + (uint32_t)(a_krow * KSTR + wid * 16 + a_ncol) * 2;
    const int b_row_off = (lane & 7);
    const int b_col_off = ((lane >> 3) & 1) * 8;
    const int g = lane >> 2, t = lane & 3;
    const int r0 = wid * 16 + g;

    for (int p = 0; p < 3; p++) {
        float acc[16][4];
#pragma unroll
        for (int i = 0; i < 16; i++)
#pragma unroll
            for (int j = 0; j < 4; j++) acc[i][j] = 0.f;
        const uint32_t wpa = wsa + (uint32_t)(p * Cn * KSTR) * 2;
#pragma unroll
        for (int ki = 0; ki < 8; ki++) {
            uint32_t a0, a1, a2, a3;
            ldsm_x4_t(a0, a1, a2, a3, a_base + (uint32_t)(ki * 16 * KSTR) * 2);
#pragma unroll
            for (int j = 0; j < 16; j++) {
                uint32_t b0, b1;
                uint32_t ba = wpa + (uint32_t)((j * 8 + b_row_off) * KSTR + ki * 16 + b_col_off) * 2;
                ldsm_x2(b0, b1, ba);
                mma16816(acc[j], a0, a1, a2, a3, b0, b1);
            }
        }
        if (p < 2) {
            // q/k: fp8 [n][d]
            uint8_t* ob = (p == 0 ? g_q8 : g_k8) + ((size_t)b * Nn + n0) * Cn;
#pragma unroll
            for (int j = 0; j < 16; j++) {
                int col = j * 8 + t * 2;
                *(uint16_t*)(ob + (size_t)r0 * Cn + col)       = e4m3x2(acc[j][0], acc[j][1]);
                *(uint16_t*)(ob + (size_t)(r0 + 8) * Cn + col) = e4m3x2(acc[j][2], acc[j][3]);
            }
        } else {
            // v: fp8 transposed [d][perm(m)]
            uint8_t* ob = g_vt + (size_t)b * Cn * Nn;
            const int m0p = n0 + wid * 16 + finv8(g);      // perm(n0 + r0)
            const int m1p = m0p + 2;                        // perm(n0 + r0 + 8)
#pragma unroll
            for (int j = 0; j < 16; j++) {
                int d0 = j * 8 + t * 2;
                ob[(size_t)d0 * Nn + m0p]       = e4m3_1(acc[j][0]);
                ob[(size_t)(d0 + 1) * Nn + m0p] = e4m3_1(acc[j][1]);
                ob[(size_t)d0 * Nn + m1p]       = e4m3_1(acc[j][2]);
                ob[(size_t)(d0 + 1) * Nn + m1p] = e4m3_1(acc[j][3]);
            }
        }
    }
}

// ---------------- kernel 3: fp8 flash attention, double-buffered, 2 CTAs/SM -------
// grid (N/BM, B), 8 warps; warp w owns query rows [w*16, w*16+16)
__global__ __launch_bounds__(256, 2)
void flash_kernel(const float* __restrict__ x, const float* __restrict__ gamma_p,
                  float* __restrict__ out) {
    extern __shared__ char smem[];
    uint8_t* sQ  = (uint8_t*)smem;                // [128][QS]
    uint8_t* sST = sQ + BM * QS;                  // 2 stages: { K[64][QS], vT[128][VS] }
    float* sO = (float*)smem;                     // epilogue union [128][SOSTR]
    constexpr int STAGE = BN * QS + Cn * VS;      // 9216 + 10240

    const int b   = blockIdx.y;
    const int n0  = blockIdx.x * BM;
    const int tid = threadIdx.x;
    const int wid = tid >> 5;
    const int lane = tid & 31;

    const uint8_t* gQ = g_q8 + ((size_t)b * Nn + n0) * Cn;
    const uint8_t* gK = g_k8 + (size_t)b * Nn * Cn;
    const uint8_t* gVT = g_vt + (size_t)b * Cn * Nn;

    // async Q tile load (128 rows x 128 B)
#pragma unroll
    for (int i = 0; i < 4; i++) {
        int idx = tid + i * 256;   // 0..1023
        int r = idx >> 3;
        int c = (idx & 7) * 16;
        cp_async16(smem_u32(sQ + r * QS + c), gQ + (size_t)r * Cn + c);
    }
    // K/V tile 0 into stage 0
    {
        uint8_t* dK = sST;
        uint8_t* dV = sST + BN * QS;
#pragma unroll
        for (int i = 0; i < 2; i++) {
            int idx = tid + i * 256;  // 0..511
            int r = idx >> 3;
            int c = (idx & 7) * 16;
            cp_async16(smem_u32(dK + r * QS + c), gK + (size_t)r * Cn + c);
            int vr = idx >> 2;
            int vc = (idx & 3) * 16;
            cp_async16(smem_u32(dV + vr * VS + vc), gVT + (size_t)vr * Nn + vc);
        }
        cp_commit();
    }

    float o_acc[16][4];
#pragma unroll
    for (int i = 0; i < 16; i++)
#pragma unroll
        for (int j = 0; j < 4; j++) o_acc[i][j] = 0.f;

    float l0p = 0.f, l1p = 0.f;

    const uint32_t sQa  = smem_u32(sQ);
    const uint32_t sSTa = smem_u32(sST);

    // fragment address bases (byte units)
    const int q_row = wid * 16 + ((lane >> 3) & 1) * 8 + (lane & 7);
    const uint32_t a_base = sQa + (uint32_t)(q_row * QS) + ((lane >> 4) & 1) * 16;
    const uint32_t k_off = (uint32_t)((((lane >> 4) & 1) * 8 + (lane & 7)) * QS) +
                           ((lane >> 3) & 1) * 16;
    const uint32_t v_off = (uint32_t)((((lane >> 4) & 1) * 8 + (lane & 7)) * VS) +
                           ((lane >> 3) & 1) * 16;

    constexpr float ESC = 1.0f / 256.0f;  // undo 16x16 operand scaling before exp
    constexpr int T = Nn / BN;
    for (int it = 0; it < T; it++) {
        const int cur = it & 1;
        if (it + 1 < T) {
            uint8_t* dK = sST + ((it + 1) & 1) * STAGE;
            uint8_t* dV = dK + BN * QS;
            const uint8_t* sgK = gK + (size_t)(it + 1) * BN * Cn;
            const uint8_t* sgV = gVT + (size_t)(it + 1) * BN;
#pragma unroll
            for (int i = 0; i < 2; i++) {
                int idx = tid + i * 256;
                int r = idx >> 3;
                int c = (idx & 7) * 16;
                cp_async16(smem_u32(dK + r * QS + c), sgK + (size_t)r * Cn + c);
                int vr = idx >> 2;
                int vc = (idx & 3) * 16;
                cp_async16(smem_u32(dV + vr * VS + vc), sgV + (size_t)vr * Nn + vc);
            }
            cp_commit();
            cp_wait<1>();
        } else {
            cp_wait<0>();
        }
        __syncthreads();

        const uint32_t sKa = sSTa + cur * STAGE;
        const uint32_t sVa = sKa + BN * QS;

        // ---- S = Q @ K^T (16 x 64 per warp), fp8 m16n8k32 ----
        float s[8][4];
#pragma unroll
        for (int j = 0; j < 8; j++)
#pragma unroll
            for (int q = 0; q < 4; q++) s[j][q] = 0.f;

#pragma unroll
        for (int ki = 0; ki < 4; ki++) {
            uint32_t a0, a1, a2, a3;
            ldsm_x4(a0, a1, a2, a3, a_base + ki * 32);
#pragma unroll
            for (int jp = 0; jp < 8; jp += 2) {
                uint32_t b0, b1, b2, b3;
                ldsm_x4(b0, b1, b2, b3, sKa + k_off + (uint32_t)(jp * 8 * QS) + ki * 32);
                mma16832(s[jp],     a0, a1, a2, a3, b0, b1);
                mma16832(s[jp + 1], a0, a1, a2, a3, b2, b3);
            }
        }

        // ---- softmax numerator (energy O(1): no max needed) ----
#pragma unroll
        for (int j = 0; j < 8; j++) {
            s[j][0] = __expf(s[j][0] * ESC);
            s[j][1] = __expf(s[j][1] * ESC);
            s[j][2] = __expf(s[j][2] * ESC);
            s[j][3] = __expf(s[j][3] * ESC);
            l0p += s[j][0] + s[j][1];
            l1p += s[j][2] + s[j][3];
        }

        // ---- pack P to fp8 A-fragments (key order absorbed by V permutation) ----
        uint32_t plo[4], phi[4];
#pragma unroll
        for (int gI = 0; gI < 4; gI++) {
            plo[gI] = e4m3x4(s[2 * gI][0], s[2 * gI][1], s[2 * gI + 1][0], s[2 * gI + 1][1]);
            phi[gI] = e4m3x4(s[2 * gI][2], s[2 * gI][3], s[2 * gI + 1][2], s[2 * gI + 1][3]);
        }

        // ---- O += P @ V  (vT in smem: [d row][key col]) ----
#pragma unroll
        for (int kc = 0; kc < 2; kc++) {
            uint32_t pa0 = plo[2 * kc], pa1 = phi[2 * kc];
            uint32_t pa2 = plo[2 * kc + 1], pa3 = phi[2 * kc + 1];
#pragma unroll
            for (int np = 0; np < 8; np++) {
                uint32_t b0, b1, b2, b3;
                ldsm_x4(b0, b1, b2, b3, sVa + v_off + (uint32_t)(np * 16 * VS) + kc * 32);
                mma16832(o_acc[2 * np],     pa0, pa1, pa2, pa3, b0, b1);
                mma16832(o_acc[2 * np + 1], pa0, pa1, pa2, pa3, b2, b3);
            }
        }
        __syncthreads();  // all warps done reading 'cur' before overwrite
    }

    // ---- reduce l across quads, finalize (1/16 undoes v scaling), fused epilogue ----
    l0p += __shfl_xor_sync(0xffffffffu, l0p, 1);
    l0p += __shfl_xor_sync(0xffffffffu, l0p, 2);
    l1p += __shfl_xor_sync(0xffffffffu, l1p, 1);
    l1p += __shfl_xor_sync(0xffffffffu, l1p, 2);
    const float il0 = 0.0625f / l0p, il1 = 0.0625f / l1p;
    const int g = lane >> 2, t = lane & 3;
    const int r0 = wid * 16 + g;
#pragma unroll
    for (int cI = 0; cI < 16; cI++) {
        int col = cI * 8 + t * 2;
        sO[r0 * SOSTR + col]           = o_acc[cI][0] * il0;
        sO[r0 * SOSTR + col + 1]       = o_acc[cI][1] * il0;
        sO[(r0 + 8) * SOSTR + col]     = o_acc[cI][2] * il1;
        sO[(r0 + 8) * SOSTR + col + 1] = o_acc[cI][3] * il1;
    }
    __syncthreads();
    const float gm = __ldg(gamma_p);
    const float* xb = x   + (size_t)b * Cn * Nn + n0;
    float*       ob = out + (size_t)b * Cn * Nn + n0;
#pragma unroll
    for (int i = 0; i < 64; i++) {
        int idx = tid + i * 256;
        int c    = idx >> 7;
        int mrow = idx & 127;
        ob[(size_t)c * Nn + mrow] = gm * sO[mrow * SOSTR + c] + xb[(size_t)c * Nn + mrow];
    }
}

// ---------------- launch ----------------
extern "C" void kernel_launch(void* const* d_in, const int* in_sizes, int n_in,
                              void* d_out, int out_size) {
    const float* x   = (const float*)d_in[0];
    const float* dwq = (const float*)d_in[1];
    const float* pwq = (const float*)d_in[2];
    const float* dwk = (const float*)d_in[3];
    const float* pwk = (const float*)d_in[4];
    const float* dwv = (const float*)d_in[5];
    const float* pwv = (const float*)d_in[6];
    const float* gm  = (const float*)d_in[7];
    float* out = (float*)d_out;

    const int proj_smem = 4 * Cn * KSTR * (int)sizeof(__nv_bfloat16);            // 139,264 B
    const int flash_core = BM * QS + 2 * (BN * QS + Cn * VS);                    // 57,344 B
    const int flash_epi  = 128 * SOSTR * (int)sizeof(float);                     // 68,096 B
    const int flash_smem = flash_core > flash_epi ? flash_core : flash_epi;

    cudaFuncSetAttribute(proj_kernel,  cudaFuncAttributeMaxDynamicSharedMemorySize, proj_smem);
    cudaFuncSetAttribute(flash_kernel, cudaFuncAttributeMaxDynamicSharedMemorySize, flash_smem);

    prep_weights_kernel<<<(3 * Cn * Cn + 255) / 256, 256>>>(pwq, dwq, pwk, dwk, pwv, dwv);
    proj_kernel<<<dim3(Nn / 128, Bn), 256, proj_smem>>>(x);
    flash_kernel<<<dim3(Nn / BM, Bn), 256, flash_smem>>>(x, gm, out);
}

// round 10
// speedup vs baseline: 1.2686x; 1.2686x over previous
#include <cuda_runtime.h>
#include <cuda_bf16.h>
#include <stdint.h>

#define DINL static __device__ __forceinline__

namespace {
constexpr int Bn = 8;
constexpr int Cn = 128;
constexpr int Nn = 4096;
constexpr int BM = 128;    // query rows per CTA
constexpr int BN = 64;     // keys per iteration
constexpr int QSTR = 136;  // bf16 smem row stride (conflict-free for ldmatrix)
constexpr int SOSTR = 133; // fp32 epilogue smem stride
constexpr int KSTR = 136;  // proj smem stride
}

// -------- scratch (no allocations allowed) --------
__device__ __align__(128) __nv_bfloat16 g_q[(size_t)Bn * Nn * Cn];
__device__ __align__(128) __nv_bfloat16 g_k[(size_t)Bn * Nn * Cn];
__device__ __align__(128) __nv_bfloat16 g_v[(size_t)Bn * Nn * Cn];
__device__ __align__(128) __nv_bfloat16 g_w2[3 * Cn * Cn];  // [p][o][k] = pw*dw (k-proj x log2e)

// ---------------- PTX helpers ----------------
DINL uint32_t smem_u32(const void* p) { return (uint32_t)__cvta_generic_to_shared(p); }

DINL void ldsm_x4(uint32_t& r0, uint32_t& r1, uint32_t& r2, uint32_t& r3, uint32_t a) {
    asm volatile("ldmatrix.sync.aligned.m8n8.x4.shared.b16 {%0,%1,%2,%3}, [%4];"
                 : "=r"(r0), "=r"(r1), "=r"(r2), "=r"(r3) : "r"(a));
}
DINL void ldsm_x4_t(uint32_t& r0, uint32_t& r1, uint32_t& r2, uint32_t& r3, uint32_t a) {
    asm volatile("ldmatrix.sync.aligned.m8n8.x4.trans.shared.b16 {%0,%1,%2,%3}, [%4];"
                 : "=r"(r0), "=r"(r1), "=r"(r2), "=r"(r3) : "r"(a));
}
DINL void mma16816(float* c, uint32_t a0, uint32_t a1, uint32_t a2, uint32_t a3,
                   uint32_t b0, uint32_t b1) {
    asm volatile("mma.sync.aligned.m16n8k16.row.col.f32.bf16.bf16.f32 "
                 "{%0,%1,%2,%3}, {%4,%5,%6,%7}, {%8,%9}, {%0,%1,%2,%3};"
                 : "+f"(c[0]), "+f"(c[1]), "+f"(c[2]), "+f"(c[3])
                 : "r"(a0), "r"(a1), "r"(a2), "r"(a3), "r"(b0), "r"(b1));
}
DINL uint32_t pack_bf16(float lo, float hi) {
    uint32_t r;
    asm("cvt.rn.bf16x2.f32 %0, %1, %2;" : "=r"(r) : "f"(hi), "f"(lo));
    return r;
}
DINL void cp_async16(uint32_t saddr, const void* gptr) {
    asm volatile("cp.async.cg.shared.global [%0], [%1], 16;" :: "r"(saddr), "l"(gptr));
}
DINL void cp_commit() { asm volatile("cp.async.commit_group;"); }
template <int N> DINL void cp_wait() { asm volatile("cp.async.wait_group %0;" :: "n"(N)); }

// ---------------- kernel 1: fold dw into pw (bf16, [p][o][k]) ----------------
// k-projection additionally scaled by log2(e) so flash can use exp2f directly.
__global__ void prep_weights_kernel(const float* __restrict__ pwq, const float* __restrict__ dwq,
                                    const float* __restrict__ pwk, const float* __restrict__ dwk,
                                    const float* __restrict__ pwv, const float* __restrict__ dwv) {
    int idx = blockIdx.x * blockDim.x + threadIdx.x;
    if (idx >= 3 * Cn * Cn) return;
    int p = idx / (Cn * Cn);
    int r = idx - p * (Cn * Cn);
    int o = r / Cn;
    int k = r - o * Cn;
    const float* pw = (p == 0) ? pwq : (p == 1 ? pwk : pwv);
    const float* dw = (p == 0) ? dwq : (p == 1 ? dwk : dwv);
    float scale = (p == 1) ? 1.4426950408889634f : 1.0f;
    g_w2[idx] = __float2bfloat16(pw[o * Cn + k] * dw[k] * scale);
}

// ---------------- kernel 2: q/k/v projections on tensor cores (2 CTAs/SM) ------
__global__ __launch_bounds__(256, 2)
void proj_kernel(const float* __restrict__ x) {
    extern __shared__ char smraw[];
    __nv_bfloat16* xs = (__nv_bfloat16*)smraw;     // [128 k][KSTR]
    __nv_bfloat16* ws = xs + Cn * KSTR;            // [128 o][KSTR]  (one proj at a time)
    const int b   = blockIdx.y;
    const int n0  = blockIdx.x * 128;
    const int tid = threadIdx.x;
    const int wid = tid >> 5;
    const int lane = tid & 31;

    // load x tile fp32 [c][n] -> bf16 [k][n]
    const float* xb = x + (size_t)b * Cn * Nn + n0;
#pragma unroll
    for (int i = 0; i < 16; i++) {
        int idx = tid + i * 256;
        int row = idx >> 5;
        int n4  = (idx & 31) * 4;
        float4 v = *(const float4*)(xb + (size_t)row * Nn + n4);
        *(uint2*)&xs[row * KSTR + n4] = make_uint2(pack_bf16(v.x, v.y), pack_bf16(v.z, v.w));
    }

    const uint32_t xsa = smem_u32(xs);
    const uint32_t wsa = smem_u32(ws);
    const int a_krow = ((lane >> 4) & 1) * 8 + (lane & 7);
    const int a_ncol = ((lane >> 3) & 1) * 8;
    const uint32_t a_base = xsa + (uint32_t)(a_krow * KSTR + wid * 16 + a_ncol) * 2;
    const int b_row = ((lane >> 4) & 1) * 8 + (lane & 7);
    const int b_col = ((lane >> 3) & 1) * 8;
    const int g = lane >> 2, t = lane & 3;
    const int r0 = wid * 16 + g;

    for (int p = 0; p < 3; p++) {
        __syncthreads();   // previous p done reading ws (and, at p=0, xs stores done)
        const __nv_bfloat16* wt = g_w2 + (size_t)p * Cn * Cn;
#pragma unroll
        for (int i = 0; i < 8; i++) {
            int idx = tid + i * 256;           // 0..2047 uint4s = 128 rows x 16
            int o  = idx >> 4;
            int c8 = (idx & 15) * 8;
            *(uint4*)&ws[o * KSTR + c8] = *(const uint4*)(wt + (size_t)o * Cn + c8);
        }
        __syncthreads();

        float acc[16][4];
#pragma unroll
        for (int i = 0; i < 16; i++)
#pragma unroll
            for (int j = 0; j < 4; j++) acc[i][j] = 0.f;
#pragma unroll
        for (int ki = 0; ki < 8; ki++) {
            uint32_t a0, a1, a2, a3;
            ldsm_x4_t(a0, a1, a2, a3, a_base + (uint32_t)(ki * 16 * KSTR) * 2);
#pragma unroll
            for (int j = 0; j < 16; j += 2) {
                uint32_t b0, b1, b2, b3;
                uint32_t ba = wsa +
                    (uint32_t)(((j * 8) + b_row) * KSTR + ki * 16 + b_col) * 2;
                ldsm_x4(b0, b1, b2, b3, ba);
                mma16816(acc[j],     a0, a1, a2, a3, b0, b1);
                mma16816(acc[j + 1], a0, a1, a2, a3, b2, b3);
            }
        }
        __nv_bfloat16* gout = (p == 0) ? g_q : (p == 1 ? g_k : g_v);
        __nv_bfloat16* obase = gout + ((size_t)b * Nn + n0) * Cn;
#pragma unroll
        for (int j = 0; j < 16; j++) {
            int col = j * 8 + t * 2;
            *(uint32_t*)(obase + (size_t)r0 * Cn + col)       = pack_bf16(acc[j][0], acc[j][1]);
            *(uint32_t*)(obase + (size_t)(r0 + 8) * Cn + col) = pack_bf16(acc[j][2], acc[j][3]);
        }
    }
}

// ---------------- kernel 3: flash attention (no-max softmax), 2 CTAs/SM ----------
// grid (N/BM, B), 8 warps; warp w owns query rows [w*16, w*16+16)
__global__ __launch_bounds__(256, 2)
void flash_kernel(const float* __restrict__ x, const float* __restrict__ gamma_p,
                  float* __restrict__ out) {
    extern __shared__ char smem[];
    __nv_bfloat16* sQ  = (__nv_bfloat16*)smem;   // [BM][QSTR]
    __nv_bfloat16* sKV = sQ + BM * QSTR;         // 2 x { K[BN][QSTR], V[BN][QSTR] }
    float* sO = (float*)smem;                    // epilogue union [128][SOSTR]

    const int b   = blockIdx.y;
    const int n0  = blockIdx.x * BM;
    const int tid = threadIdx.x;
    const int wid = tid >> 5;
    const int lane = tid & 31;

    const __nv_bfloat16* gQ = g_q + ((size_t)b * Nn + n0) * Cn;
    const __nv_bfloat16* gK = g_k + (size_t)b * Nn * Cn;
    const __nv_bfloat16* gV = g_v + (size_t)b * Nn * Cn;

    // async Q tile load (group 0, together with KV tile 0)
#pragma unroll
    for (int i = 0; i < 8; i++) {
        int idx = tid + i * 256;
        int r = idx >> 4;
        int c = (idx & 15) * 8;
        cp_async16(smem_u32(sQ + r * QSTR + c), gQ + (size_t)r * Cn + c);
    }
    {
        __nv_bfloat16* dK = sKV;
        __nv_bfloat16* dV = sKV + BN * QSTR;
#pragma unroll
        for (int i = 0; i < 4; i++) {
            int idx = tid + i * 256;
            int r = idx >> 4;
            int c = (idx & 15) * 8;
            cp_async16(smem_u32(dK + r * QSTR + c), gK + (size_t)r * Cn + c);
            cp_async16(smem_u32(dV + r * QSTR + c), gV + (size_t)r * Cn + c);
        }
        cp_commit();
    }

    float o_acc[16][4];
#pragma unroll
    for (int i = 0; i < 16; i++)
#pragma unroll
        for (int j = 0; j < 4; j++) o_acc[i][j] = 0.f;

    float l0a = 0.f, l0b = 0.f, l1a = 0.f, l1b = 0.f;  // split partial row sums

    const uint32_t sQa   = smem_u32(sQ);
    const uint32_t sKV0a = smem_u32(sKV);

    const int q_row       = wid * 16 + ((lane >> 3) & 1) * 8 + (lane & 7);
    const uint32_t a_base = sQa + (uint32_t)(q_row * QSTR + (lane >> 4) * 8) * 2;
    const int k4_rowoff = ((lane >> 4) & 1) * 8 + (lane & 7);
    const int k4_col    = ((lane >> 3) & 1) * 8;
    const int v4_row    = ((lane >> 3) & 1) * 8 + (lane & 7);
    const int v4_csel   = (lane >> 4) & 1;

    constexpr int T = Nn / BN;
    for (int it = 0; it < T; it++) {
        const int cur = it & 1;
        cp_wait<0>();
        __syncthreads();   // tile `it` visible to all; all warps finished iter it-1

        if (it + 1 < T) {  // prefetch overlaps this iteration's compute
            __nv_bfloat16* dK = sKV + ((it + 1) & 1) * (2 * BN * QSTR);
            __nv_bfloat16* dV = dK + BN * QSTR;
            const __nv_bfloat16* sgK = gK + (size_t)(it + 1) * BN * Cn;
            const __nv_bfloat16* sgV = gV + (size_t)(it + 1) * BN * Cn;
#pragma unroll
            for (int i = 0; i < 4; i++) {
                int idx = tid + i * 256;
                int r = idx >> 4;
                int c = (idx & 15) * 8;
                cp_async16(smem_u32(dK + r * QSTR + c), sgK + (size_t)r * Cn + c);
                cp_async16(smem_u32(dV + r * QSTR + c), sgV + (size_t)r * Cn + c);
            }
            cp_commit();
        }

        const uint32_t sKa = sKV0a + (uint32_t)(cur * 2 * BN * QSTR) * 2;
        const uint32_t sVa = sKa + (uint32_t)(BN * QSTR) * 2;

        // ---- S = Q @ K^T (16 x 64 per warp) ----
        float s[8][4];
#pragma unroll
        for (int j = 0; j < 8; j++)
#pragma unroll
            for (int q = 0; q < 4; q++) s[j][q] = 0.f;

#pragma unroll
        for (int ki = 0; ki < 8; ki++) {
            uint32_t a0, a1, a2, a3;
            ldsm_x4(a0, a1, a2, a3, a_base + ki * 32);
#pragma unroll
            for (int j = 0; j < 8; j += 2) {
                uint32_t b0, b1, b2, b3;
                uint32_t ka = sKa +
                    (uint32_t)((j * 8 + k4_rowoff) * QSTR + ki * 16 + k4_col) * 2;
                ldsm_x4(b0, b1, b2, b3, ka);
                mma16816(s[j],     a0, a1, a2, a3, b0, b1);
                mma16816(s[j + 1], a0, a1, a2, a3, b2, b3);
            }
        }

        // ---- softmax numerator: 2^s  (log2e folded into k weights) ----
#pragma unroll
        for (int j = 0; j < 8; j++) {
            s[j][0] = exp2f(s[j][0]);
            s[j][1] = exp2f(s[j][1]);
            s[j][2] = exp2f(s[j][2]);
            s[j][3] = exp2f(s[j][3]);
            l0a += s[j][0]; l0b += s[j][1];
            l1a += s[j][2]; l1b += s[j][3];
        }

        // ---- O += P @ V ----
#pragma unroll
        for (int s4 = 0; s4 < 4; s4++) {
            uint32_t pa0 = pack_bf16(s[2 * s4][0],     s[2 * s4][1]);
            uint32_t pa1 = pack_bf16(s[2 * s4][2],     s[2 * s4][3]);
            uint32_t pa2 = pack_bf16(s[2 * s4 + 1][0], s[2 * s4 + 1][1]);
            uint32_t pa3 = pack_bf16(s[2 * s4 + 1][2], s[2 * s4 + 1][3]);
            uint32_t vrow = (uint32_t)(s4 * 16 + v4_row) * QSTR;
#pragma unroll
            for (int cI = 0; cI < 16; cI += 2) {
                uint32_t b0, b1, b2, b3;
                ldsm_x4_t(b0, b1, b2, b3, sVa + (vrow + (cI + v4_csel) * 8) * 2);
                mma16816(o_acc[cI],     pa0, pa1, pa2, pa3, b0, b1);
                mma16816(o_acc[cI + 1], pa0, pa1, pa2, pa3, b2, b3);
            }
        }
        // no trailing barrier: next iteration's top barrier provides the guarantee
    }

    // ---- reduce l across quads, fold gamma into normalizer, fused epilogue ----
    float l0p = l0a + l0b, l1p = l1a + l1b;
    l0p += __shfl_xor_sync(0xffffffffu, l0p, 1);
    l0p += __shfl_xor_sync(0xffffffffu, l0p, 2);
    l1p += __shfl_xor_sync(0xffffffffu, l1p, 1);
    l1p += __shfl_xor_sync(0xffffffffu, l1p, 2);
    const float gm = __ldg(gamma_p);
    const float il0 = gm / l0p, il1 = gm / l1p;
    const int g = lane >> 2, t = lane & 3;
    const int r0 = wid * 16 + g;
    __syncthreads();   // all warps done reading K/V smem before sO overwrites it
#pragma unroll
    for (int cI = 0; cI < 16; cI++) {
        int col = cI * 8 + t * 2;
        sO[r0 * SOSTR + col]           = o_acc[cI][0] * il0;
        sO[r0 * SOSTR + col + 1]       = o_acc[cI][1] * il0;
        sO[(r0 + 8) * SOSTR + col]     = o_acc[cI][2] * il1;
        sO[(r0 + 8) * SOSTR + col + 1] = o_acc[cI][3] * il1;
    }
    __syncthreads();
    const float* xb = x   + (size_t)b * Cn * Nn + n0;
    float*       ob = out + (size_t)b * Cn * Nn + n0;
#pragma unroll
    for (int i = 0; i < 64; i++) {
        int idx = tid + i * 256;
        int c    = idx >> 7;
        int mrow = idx & 127;
        ob[(size_t)c * Nn + mrow] = sO[mrow * SOSTR + c] + xb[(size_t)c * Nn + mrow];
    }
}

// ---------------- launch ----------------
extern "C" void kernel_launch(void* const* d_in, const int* in_sizes, int n_in,
                              void* d_out, int out_size) {
    const float* x   = (const float*)d_in[0];
    const float* dwq = (const float*)d_in[1];
    const float* pwq = (const float*)d_in[2];
    const float* dwk = (const float*)d_in[3];
    const float* pwk = (const float*)d_in[4];
    const float* dwv = (const float*)d_in[5];
    const float* pwv = (const float*)d_in[6];
    const float* gm  = (const float*)d_in[7];
    float* out = (float*)d_out;

    const int proj_smem  = 2 * Cn * KSTR * (int)sizeof(__nv_bfloat16);                 // 69,632 B
    const int flash_smem = (BM * QSTR + 4 * BN * QSTR) * (int)sizeof(__nv_bfloat16);   // 104,448 B

    cudaFuncSetAttribute(proj_kernel,  cudaFuncAttributeMaxDynamicSharedMemorySize, proj_smem);
    cudaFuncSetAttribute(flash_kernel, cudaFuncAttributeMaxDynamicSharedMemorySize, flash_smem);

    prep_weights_kernel<<<(3 * Cn * Cn + 255) / 256, 256>>>(pwq, dwq, pwk, dwk, pwv, dwv);
    proj_kernel<<<dim3(Nn / 128, Bn), 256, proj_smem>>>(x);
    flash_kernel<<<dim3(Nn / BM, Bn), 256, flash_smem>>>(x, gm, out);
}

// round 11
// speedup vs baseline: 1.3619x; 1.0736x over previous
#include <cuda_runtime.h>
#include <cuda_bf16.h>
#include <stdint.h>

#define DINL static __device__ __forceinline__

namespace {
constexpr int Bn = 8;
constexpr int Cn = 128;
constexpr int Nn = 4096;
constexpr int BM = 128;    // query rows per CTA
constexpr int BN = 64;     // keys per iteration
constexpr int QSTR = 136;  // bf16 smem row stride (conflict-free for ldmatrix)
constexpr int SOSTR = 133; // fp32 epilogue smem stride
constexpr int KSTR = 136;  // proj smem stride
}

// -------- scratch (no allocations allowed) --------
__device__ __align__(128) __nv_bfloat16 g_q[(size_t)Bn * Nn * Cn];
__device__ __align__(128) __nv_bfloat16 g_k[(size_t)Bn * Nn * Cn];
__device__ __align__(128) __nv_bfloat16 g_v[(size_t)Bn * Nn * Cn];
__device__ __align__(128) __nv_bfloat16 g_w2[3 * Cn * Cn];  // [p][o][k] = pw*dw (k-proj x log2e)

// ---------------- PTX helpers ----------------
DINL uint32_t smem_u32(const void* p) { return (uint32_t)__cvta_generic_to_shared(p); }

DINL void ldsm_x4(uint32_t& r0, uint32_t& r1, uint32_t& r2, uint32_t& r3, uint32_t a) {
    asm volatile("ldmatrix.sync.aligned.m8n8.x4.shared.b16 {%0,%1,%2,%3}, [%4];"
                 : "=r"(r0), "=r"(r1), "=r"(r2), "=r"(r3) : "r"(a));
}
DINL void ldsm_x4_t(uint32_t& r0, uint32_t& r1, uint32_t& r2, uint32_t& r3, uint32_t a) {
    asm volatile("ldmatrix.sync.aligned.m8n8.x4.trans.shared.b16 {%0,%1,%2,%3}, [%4];"
                 : "=r"(r0), "=r"(r1), "=r"(r2), "=r"(r3) : "r"(a));
}
DINL void mma16816(float* c, uint32_t a0, uint32_t a1, uint32_t a2, uint32_t a3,
                   uint32_t b0, uint32_t b1) {
    asm volatile("mma.sync.aligned.m16n8k16.row.col.f32.bf16.bf16.f32 "
                 "{%0,%1,%2,%3}, {%4,%5,%6,%7}, {%8,%9}, {%0,%1,%2,%3};"
                 : "+f"(c[0]), "+f"(c[1]), "+f"(c[2]), "+f"(c[3])
                 : "r"(a0), "r"(a1), "r"(a2), "r"(a3), "r"(b0), "r"(b1));
}
DINL uint32_t pack_bf16(float lo, float hi) {
    uint32_t r;
    asm("cvt.rn.bf16x2.f32 %0, %1, %2;" : "=r"(r) : "f"(hi), "f"(lo));
    return r;
}
DINL void cp_async16(uint32_t saddr, const void* gptr) {
    asm volatile("cp.async.cg.shared.global [%0], [%1], 16;" :: "r"(saddr), "l"(gptr));
}
DINL void cp_commit() { asm volatile("cp.async.commit_group;"); }
template <int N> DINL void cp_wait() { asm volatile("cp.async.wait_group %0;" :: "n"(N)); }

// ---------------- kernel 1: fold dw into pw (bf16, [p][o][k]) ----------------
__global__ void prep_weights_kernel(const float* __restrict__ pwq, const float* __restrict__ dwq,
                                    const float* __restrict__ pwk, const float* __restrict__ dwk,
                                    const float* __restrict__ pwv, const float* __restrict__ dwv) {
    int idx = blockIdx.x * blockDim.x + threadIdx.x;
    if (idx >= 3 * Cn * Cn) return;
    int p = idx / (Cn * Cn);
    int r = idx - p * (Cn * Cn);
    int o = r / Cn;
    int k = r - o * Cn;
    const float* pw = (p == 0) ? pwq : (p == 1 ? pwk : pwv);
    const float* dw = (p == 0) ? dwq : (p == 1 ? dwk : dwv);
    float scale = (p == 1) ? 1.4426950408889634f : 1.0f;
    g_w2[idx] = __float2bfloat16(pw[o * Cn + k] * dw[k] * scale);
}

// ---------------- kernel 2: q/k/v projections on tensor cores (2 CTAs/SM) ------
__global__ __launch_bounds__(256, 2)
void proj_kernel(const float* __restrict__ x) {
    extern __shared__ char smraw[];
    __nv_bfloat16* xs = (__nv_bfloat16*)smraw;     // [128 k][KSTR]
    __nv_bfloat16* ws = xs + Cn * KSTR;            // [128 o][KSTR]
    const int b   = blockIdx.y;
    const int n0  = blockIdx.x * 128;
    const int tid = threadIdx.x;
    const int wid = tid >> 5;
    const int lane = tid & 31;

    const float* xb = x + (size_t)b * Cn * Nn + n0;
#pragma unroll
    for (int i = 0; i < 16; i++) {
        int idx = tid + i * 256;
        int row = idx >> 5;
        int n4  = (idx & 31) * 4;
        float4 v = *(const float4*)(xb + (size_t)row * Nn + n4);
        *(uint2*)&xs[row * KSTR + n4] = make_uint2(pack_bf16(v.x, v.y), pack_bf16(v.z, v.w));
    }

    const uint32_t xsa = smem_u32(xs);
    const uint32_t wsa = smem_u32(ws);
    const int a_krow = ((lane >> 4) & 1) * 8 + (lane & 7);
    const int a_ncol = ((lane >> 3) & 1) * 8;
    const uint32_t a_base = xsa + (uint32_t)(a_krow * KSTR + wid * 16 + a_ncol) * 2;
    const int b_row = ((lane >> 4) & 1) * 8 + (lane & 7);
    const int b_col = ((lane >> 3) & 1) * 8;
    const int g = lane >> 2, t = lane & 3;
    const int r0 = wid * 16 + g;

    for (int p = 0; p < 3; p++) {
        __syncthreads();
        const __nv_bfloat16* wt = g_w2 + (size_t)p * Cn * Cn;
#pragma unroll
        for (int i = 0; i < 8; i++) {
            int idx = tid + i * 256;
            int o  = idx >> 4;
            int c8 = (idx & 15) * 8;
            *(uint4*)&ws[o * KSTR + c8] = *(const uint4*)(wt + (size_t)o * Cn + c8);
        }
        __syncthreads();

        float acc[16][4];
#pragma unroll
        for (int i = 0; i < 16; i++)
#pragma unroll
            for (int j = 0; j < 4; j++) acc[i][j] = 0.f;
#pragma unroll
        for (int ki = 0; ki < 8; ki++) {
            uint32_t a0, a1, a2, a3;
            ldsm_x4_t(a0, a1, a2, a3, a_base + (uint32_t)(ki * 16 * KSTR) * 2);
#pragma unroll
            for (int j = 0; j < 16; j += 2) {
                uint32_t b0, b1, b2, b3;
                uint32_t ba = wsa +
                    (uint32_t)(((j * 8) + b_row) * KSTR + ki * 16 + b_col) * 2;
                ldsm_x4(b0, b1, b2, b3, ba);
                mma16816(acc[j],     a0, a1, a2, a3, b0, b1);
                mma16816(acc[j + 1], a0, a1, a2, a3, b2, b3);
            }
        }
        __nv_bfloat16* gout = (p == 0) ? g_q : (p == 1 ? g_k : g_v);
        __nv_bfloat16* obase = gout + ((size_t)b * Nn + n0) * Cn;
#pragma unroll
        for (int j = 0; j < 16; j++) {
            int col = j * 8 + t * 2;
            *(uint32_t*)(obase + (size_t)r0 * Cn + col)       = pack_bf16(acc[j][0], acc[j][1]);
            *(uint32_t*)(obase + (size_t)(r0 + 8) * Cn + col) = pack_bf16(acc[j][2], acc[j][3]);
        }
    }
}

// ---------------- kernel 3: flash attention, 4 warps x 32 q-rows, 2 CTAs/SM ------
// grid (N/BM, B), 128 threads; warp w owns query rows [w*32, w*32+32)
__global__ __launch_bounds__(128, 2)
void flash_kernel(const float* __restrict__ x, const float* __restrict__ gamma_p,
                  float* __restrict__ out) {
    extern __shared__ char smem[];
    __nv_bfloat16* sQ  = (__nv_bfloat16*)smem;   // [BM][QSTR]
    __nv_bfloat16* sKV = sQ + BM * QSTR;         // 2 x { K[BN][QSTR], V[BN][QSTR] }
    float* sO = (float*)smem;                    // epilogue union [128][SOSTR]

    const int b   = blockIdx.y;
    const int n0  = blockIdx.x * BM;
    const int tid = threadIdx.x;
    const int wid = tid >> 5;
    const int lane = tid & 31;

    const __nv_bfloat16* gQ = g_q + ((size_t)b * Nn + n0) * Cn;
    const __nv_bfloat16* gK = g_k + (size_t)b * Nn * Cn;
    const __nv_bfloat16* gV = g_v + (size_t)b * Nn * Cn;

    // async Q tile load (2048 uint4s over 128 threads)
#pragma unroll
    for (int i = 0; i < 16; i++) {
        int idx = tid + i * 128;
        int r = idx >> 4;
        int c = (idx & 15) * 8;
        cp_async16(smem_u32(sQ + r * QSTR + c), gQ + (size_t)r * Cn + c);
    }
    {
        __nv_bfloat16* dK = sKV;
        __nv_bfloat16* dV = sKV + BN * QSTR;
#pragma unroll
        for (int i = 0; i < 8; i++) {
            int idx = tid + i * 128;
            int r = idx >> 4;
            int c = (idx & 15) * 8;
            cp_async16(smem_u32(dK + r * QSTR + c), gK + (size_t)r * Cn + c);
            cp_async16(smem_u32(dV + r * QSTR + c), gV + (size_t)r * Cn + c);
        }
        cp_commit();
    }

    float o_acc[2][16][4];
#pragma unroll
    for (int h = 0; h < 2; h++)
#pragma unroll
        for (int i = 0; i < 16; i++)
#pragma unroll
            for (int j = 0; j < 4; j++) o_acc[h][i][j] = 0.f;

    float lA[2] = {0.f, 0.f}, lB[2] = {0.f, 0.f};  // partial row sums per half

    const uint32_t sQa   = smem_u32(sQ);
    const uint32_t sKV0a = smem_u32(sKV);

    // A-fragment bases for the two row-halves this warp owns
    const int q_sub = ((lane >> 3) & 1) * 8 + (lane & 7);
    const uint32_t a_base0 = sQa + (uint32_t)((wid * 32 + q_sub) * QSTR + (lane >> 4) * 8) * 2;
    const uint32_t a_base1 = a_base0 + (uint32_t)(16 * QSTR) * 2;
    const int k4_rowoff = ((lane >> 4) & 1) * 8 + (lane & 7);
    const int k4_col    = ((lane >> 3) & 1) * 8;
    const int v4_row    = ((lane >> 3) & 1) * 8 + (lane & 7);
    const int v4_csel   = (lane >> 4) & 1;

    constexpr int T = Nn / BN;
    for (int it = 0; it < T; it++) {
        const int cur = it & 1;
        cp_wait<0>();
        __syncthreads();

        if (it + 1 < T) {
            __nv_bfloat16* dK = sKV + ((it + 1) & 1) * (2 * BN * QSTR);
            __nv_bfloat16* dV = dK + BN * QSTR;
            const __nv_bfloat16* sgK = gK + (size_t)(it + 1) * BN * Cn;
            const __nv_bfloat16* sgV = gV + (size_t)(it + 1) * BN * Cn;
#pragma unroll
            for (int i = 0; i < 8; i++) {
                int idx = tid + i * 128;
                int r = idx >> 4;
                int c = (idx & 15) * 8;
                cp_async16(smem_u32(dK + r * QSTR + c), sgK + (size_t)r * Cn + c);
                cp_async16(smem_u32(dV + r * QSTR + c), sgV + (size_t)r * Cn + c);
            }
            cp_commit();
        }

        const uint32_t sKa = sKV0a + (uint32_t)(cur * 2 * BN * QSTR) * 2;
        const uint32_t sVa = sKa + (uint32_t)(BN * QSTR) * 2;

        // ---- S = Q @ K^T : 32 x 64 per warp (two 16-row halves share B frags) ----
        float s[2][8][4];
#pragma unroll
        for (int h = 0; h < 2; h++)
#pragma unroll
            for (int j = 0; j < 8; j++)
#pragma unroll
                for (int q = 0; q < 4; q++) s[h][j][q] = 0.f;

#pragma unroll
        for (int ki = 0; ki < 8; ki++) {
            uint32_t a00, a01, a02, a03, a10, a11, a12, a13;
            ldsm_x4(a00, a01, a02, a03, a_base0 + ki * 32);
            ldsm_x4(a10, a11, a12, a13, a_base1 + ki * 32);
#pragma unroll
            for (int j = 0; j < 8; j += 2) {
                uint32_t b0, b1, b2, b3;
                uint32_t ka = sKa +
                    (uint32_t)((j * 8 + k4_rowoff) * QSTR + ki * 16 + k4_col) * 2;
                ldsm_x4(b0, b1, b2, b3, ka);
                mma16816(s[0][j],     a00, a01, a02, a03, b0, b1);
                mma16816(s[0][j + 1], a00, a01, a02, a03, b2, b3);
                mma16816(s[1][j],     a10, a11, a12, a13, b0, b1);
                mma16816(s[1][j + 1], a10, a11, a12, a13, b2, b3);
            }
        }

        // ---- softmax numerator: 2^s (log2e folded into k weights) ----
#pragma unroll
        for (int h = 0; h < 2; h++)
#pragma unroll
            for (int j = 0; j < 8; j++) {
                s[h][j][0] = exp2f(s[h][j][0]);
                s[h][j][1] = exp2f(s[h][j][1]);
                s[h][j][2] = exp2f(s[h][j][2]);
                s[h][j][3] = exp2f(s[h][j][3]);
                lA[h] += s[h][j][0] + s[h][j][1];
                lB[h] += s[h][j][2] + s[h][j][3];
            }

        // ---- O += P @ V (V frags shared across both halves) ----
#pragma unroll
        for (int s4 = 0; s4 < 4; s4++) {
            uint32_t pa[2][4];
#pragma unroll
            for (int h = 0; h < 2; h++) {
                pa[h][0] = pack_bf16(s[h][2 * s4][0],     s[h][2 * s4][1]);
                pa[h][1] = pack_bf16(s[h][2 * s4][2],     s[h][2 * s4][3]);
                pa[h][2] = pack_bf16(s[h][2 * s4 + 1][0], s[h][2 * s4 + 1][1]);
                pa[h][3] = pack_bf16(s[h][2 * s4 + 1][2], s[h][2 * s4 + 1][3]);
            }
            uint32_t vrow = (uint32_t)(s4 * 16 + v4_row) * QSTR;
#pragma unroll
            for (int cI = 0; cI < 16; cI += 2) {
                uint32_t b0, b1, b2, b3;
                ldsm_x4_t(b0, b1, b2, b3, sVa + (vrow + (cI + v4_csel) * 8) * 2);
                mma16816(o_acc[0][cI],     pa[0][0], pa[0][1], pa[0][2], pa[0][3], b0, b1);
                mma16816(o_acc[0][cI + 1], pa[0][0], pa[0][1], pa[0][2], pa[0][3], b2, b3);
                mma16816(o_acc[1][cI],     pa[1][0], pa[1][1], pa[1][2], pa[1][3], b0, b1);
                mma16816(o_acc[1][cI + 1], pa[1][0], pa[1][1], pa[1][2], pa[1][3], b2, b3);
            }
        }
    }

    // ---- reduce l across quads, fold gamma, fused epilogue ----
    const float gm = __ldg(gamma_p);
    float il0[2], il1[2];
#pragma unroll
    for (int h = 0; h < 2; h++) {
        float a = lA[h], bb = lB[h];
        a += __shfl_xor_sync(0xffffffffu, a, 1);
        a += __shfl_xor_sync(0xffffffffu, a, 2);
        bb += __shfl_xor_sync(0xffffffffu, bb, 1);
        bb += __shfl_xor_sync(0xffffffffu, bb, 2);
        il0[h] = gm / a;
        il1[h] = gm / bb;
    }
    const int g = lane >> 2, t = lane & 3;
    __syncthreads();   // all warps done with smem tiles before sO overwrites
#pragma unroll
    for (int h = 0; h < 2; h++) {
        const int r0 = wid * 32 + h * 16 + g;
#pragma unroll
        for (int cI = 0; cI < 16; cI++) {
            int col = cI * 8 + t * 2;
            sO[r0 * SOSTR + col]           = o_acc[h][cI][0] * il0[h];
            sO[r0 * SOSTR + col + 1]       = o_acc[h][cI][1] * il0[h];
            sO[(r0 + 8) * SOSTR + col]     = o_acc[h][cI][2] * il1[h];
            sO[(r0 + 8) * SOSTR + col + 1] = o_acc[h][cI][3] * il1[h];
        }
    }
    __syncthreads();
    const float* xb = x   + (size_t)b * Cn * Nn + n0;
    float*       ob = out + (size_t)b * Cn * Nn + n0;
#pragma unroll
    for (int i = 0; i < 128; i++) {
        int idx = tid + i * 128;
        int c    = idx >> 7;
        int mrow = idx & 127;
        ob[(size_t)c * Nn + mrow] = sO[mrow * SOSTR + c] + xb[(size_t)c * Nn + mrow];
    }
}

// ---------------- launch ----------------
extern "C" void kernel_launch(void* const* d_in, const int* in_sizes, int n_in,
                              void* d_out, int out_size) {
    const float* x   = (const float*)d_in[0];
    const float* dwq = (const float*)d_in[1];
    const float* pwq = (const float*)d_in[2];
    const float* dwk = (const float*)d_in[3];
    const float* pwk = (const float*)d_in[4];
    const float* dwv = (const float*)d_in[5];
    const float* pwv = (const float*)d_in[6];
    const float* gm  = (const float*)d_in[7];
    float* out = (float*)d_out;

    const int proj_smem  = 2 * Cn * KSTR * (int)sizeof(__nv_bfloat16);                 // 69,632 B
    const int flash_smem = (BM * QSTR + 4 * BN * QSTR) * (int)sizeof(__nv_bfloat16);   // 104,448 B

    cudaFuncSetAttribute(proj_kernel,  cudaFuncAttributeMaxDynamicSharedMemorySize, proj_smem);
    cudaFuncSetAttribute(flash_kernel, cudaFuncAttributeMaxDynamicSharedMemorySize, flash_smem);

    prep_weights_kernel<<<(3 * Cn * Cn + 255) / 256, 256>>>(pwq, dwq, pwk, dwk, pwv, dwv);
    proj_kernel<<<dim3(Nn / 128, Bn), 256, proj_smem>>>(x);
    flash_kernel<<<dim3(Nn / BM, Bn), 128, flash_smem>>>(x, gm, out);
}

// round 12
// speedup vs baseline: 1.4128x; 1.0373x over previous
#include <cuda_runtime.h>
#include <cuda_bf16.h>
#include <stdint.h>

#define DINL static __device__ __forceinline__

namespace {
constexpr int Bn = 8;
constexpr int Cn = 128;
constexpr int Nn = 4096;
constexpr int BM = 128;    // query rows per CTA
constexpr int BN = 64;     // keys per iteration
constexpr int QSTR = 136;  // bf16 smem row stride (conflict-free for ldmatrix)
constexpr int SOSTR = 133; // fp32 epilogue smem stride
constexpr int KSTR = 136;  // proj smem stride
constexpr int STAGE_B = 2 * BN * QSTR * 2;  // one KV stage in bytes (34,816)
}

// -------- scratch (no allocations allowed) --------
__device__ __align__(128) __nv_bfloat16 g_k[(size_t)Bn * Nn * Cn];
__device__ __align__(128) __nv_bfloat16 g_v[(size_t)Bn * Nn * Cn];
__device__ __align__(128) __nv_bfloat16 g_w2[3 * Cn * Cn];  // [p][o][k] = pw*dw (k-proj x log2e)

// ---------------- PTX helpers ----------------
DINL uint32_t smem_u32(const void* p) { return (uint32_t)__cvta_generic_to_shared(p); }

DINL void ldsm_x4(uint32_t& r0, uint32_t& r1, uint32_t& r2, uint32_t& r3, uint32_t a) {
    asm volatile("ldmatrix.sync.aligned.m8n8.x4.shared.b16 {%0,%1,%2,%3}, [%4];"
                 : "=r"(r0), "=r"(r1), "=r"(r2), "=r"(r3) : "r"(a));
}
DINL void ldsm_x4_t(uint32_t& r0, uint32_t& r1, uint32_t& r2, uint32_t& r3, uint32_t a) {
    asm volatile("ldmatrix.sync.aligned.m8n8.x4.trans.shared.b16 {%0,%1,%2,%3}, [%4];"
                 : "=r"(r0), "=r"(r1), "=r"(r2), "=r"(r3) : "r"(a));
}
DINL void mma16816(float* c, uint32_t a0, uint32_t a1, uint32_t a2, uint32_t a3,
                   uint32_t b0, uint32_t b1) {
    asm volatile("mma.sync.aligned.m16n8k16.row.col.f32.bf16.bf16.f32 "
                 "{%0,%1,%2,%3}, {%4,%5,%6,%7}, {%8,%9}, {%0,%1,%2,%3};"
                 : "+f"(c[0]), "+f"(c[1]), "+f"(c[2]), "+f"(c[3])
                 : "r"(a0), "r"(a1), "r"(a2), "r"(a3), "r"(b0), "r"(b1));
}
DINL uint32_t pack_bf16(float lo, float hi) {
    uint32_t r;
    asm("cvt.rn.bf16x2.f32 %0, %1, %2;" : "=r"(r) : "f"(hi), "f"(lo));
    return r;
}
DINL void cp_async16(uint32_t saddr, const void* gptr) {
    asm volatile("cp.async.cg.shared.global [%0], [%1], 16;" :: "r"(saddr), "l"(gptr));
}
DINL void cp_commit() { asm volatile("cp.async.commit_group;"); }
template <int N> DINL void cp_wait() { asm volatile("cp.async.wait_group %0;" :: "n"(N)); }

// ---------------- kernel 1: fold dw into pw (bf16, [p][o][k]) ----------------
__global__ void prep_weights_kernel(const float* __restrict__ pwq, const float* __restrict__ dwq,
                                    const float* __restrict__ pwk, const float* __restrict__ dwk,
                                    const float* __restrict__ pwv, const float* __restrict__ dwv) {
    int idx = blockIdx.x * blockDim.x + threadIdx.x;
    if (idx >= 3 * Cn * Cn) return;
    int p = idx / (Cn * Cn);
    int r = idx - p * (Cn * Cn);
    int o = r / Cn;
    int k = r - o * Cn;
    const float* pw = (p == 0) ? pwq : (p == 1 ? pwk : pwv);
    const float* dw = (p == 0) ? dwq : (p == 1 ? dwk : dwv);
    float scale = (p == 1) ? 1.4426950408889634f : 1.0f;
    g_w2[idx] = __float2bfloat16(pw[o * Cn + k] * dw[k] * scale);
}

// ---------------- kernel 2: k/v projections (double-buffered weights) ----------
__global__ __launch_bounds__(256, 2)
void proj_kernel(const float* __restrict__ x) {
    extern __shared__ char smraw[];
    __nv_bfloat16* xs  = (__nv_bfloat16*)smraw;      // [128 k][KSTR]
    __nv_bfloat16* ws0 = xs + Cn * KSTR;             // w_k
    __nv_bfloat16* ws1 = ws0 + Cn * KSTR;            // w_v
    const int b   = blockIdx.y;
    const int n0  = blockIdx.x * 128;
    const int tid = threadIdx.x;
    const int wid = tid >> 5;
    const int lane = tid & 31;

    // issue both weight loads (groups 0 and 1)
    const __nv_bfloat16* wk = g_w2 + (size_t)1 * Cn * Cn;
    const __nv_bfloat16* wv = g_w2 + (size_t)2 * Cn * Cn;
#pragma unroll
    for (int i = 0; i < 8; i++) {
        int idx = tid + i * 256;
        int o  = idx >> 4;
        int c8 = (idx & 15) * 8;
        cp_async16(smem_u32(ws0 + o * KSTR + c8), wk + (size_t)o * Cn + c8);
    }
    cp_commit();
#pragma unroll
    for (int i = 0; i < 8; i++) {
        int idx = tid + i * 256;
        int o  = idx >> 4;
        int c8 = (idx & 15) * 8;
        cp_async16(smem_u32(ws1 + o * KSTR + c8), wv + (size_t)o * Cn + c8);
    }
    cp_commit();

    // x tile fp32 [c][n] -> bf16 [k][n] (overlaps weight cp.async)
    const float* xb = x + (size_t)b * Cn * Nn + n0;
#pragma unroll
    for (int i = 0; i < 16; i++) {
        int idx = tid + i * 256;
        int row = idx >> 5;
        int n4  = (idx & 31) * 4;
        float4 v = *(const float4*)(xb + (size_t)row * Nn + n4);
        *(uint2*)&xs[row * KSTR + n4] = make_uint2(pack_bf16(v.x, v.y), pack_bf16(v.z, v.w));
    }

    const uint32_t xsa = smem_u32(xs);
    const int a_krow = ((lane >> 4) & 1) * 8 + (lane & 7);
    const int a_ncol = ((lane >> 3) & 1) * 8;
    const uint32_t a_base = xsa + (uint32_t)(a_krow * KSTR + wid * 16 + a_ncol) * 2;
    const int b_row = ((lane >> 4) & 1) * 8 + (lane & 7);
    const int b_col = ((lane >> 3) & 1) * 8;
    const int g = lane >> 2, t = lane & 3;
    const int r0 = wid * 16 + g;

    cp_wait<1>();
    __syncthreads();

#pragma unroll
    for (int p = 0; p < 2; p++) {
        if (p == 1) {
            cp_wait<0>();
            __syncthreads();
        }
        const uint32_t wsa = smem_u32(p == 0 ? ws0 : ws1);
        float acc[16][4];
#pragma unroll
        for (int i = 0; i < 16; i++)
#pragma unroll
            for (int j = 0; j < 4; j++) acc[i][j] = 0.f;
#pragma unroll
        for (int ki = 0; ki < 8; ki++) {
            uint32_t a0, a1, a2, a3;
            ldsm_x4_t(a0, a1, a2, a3, a_base + (uint32_t)(ki * 16 * KSTR) * 2);
#pragma unroll
            for (int j = 0; j < 16; j += 2) {
                uint32_t b0, b1, b2, b3;
                uint32_t ba = wsa +
                    (uint32_t)(((j * 8) + b_row) * KSTR + ki * 16 + b_col) * 2;
                ldsm_x4(b0, b1, b2, b3, ba);
                mma16816(acc[j],     a0, a1, a2, a3, b0, b1);
                mma16816(acc[j + 1], a0, a1, a2, a3, b2, b3);
            }
        }
        __nv_bfloat16* gout = (p == 0) ? g_k : g_v;
        __nv_bfloat16* obase = gout + ((size_t)b * Nn + n0) * Cn;
#pragma unroll
        for (int j = 0; j < 16; j++) {
            int col = j * 8 + t * 2;
            *(uint32_t*)(obase + (size_t)r0 * Cn + col)       = pack_bf16(acc[j][0], acc[j][1]);
            *(uint32_t*)(obase + (size_t)(r0 + 8) * Cn + col) = pack_bf16(acc[j][2], acc[j][3]);
        }
    }
}

// ---------------- kernel 3: flash attention w/ fused Q projection --------------
// grid (N/BM, B), 128 threads; warp w owns query rows [w*32, w*32+32)
__global__ __launch_bounds__(128, 2)
void flash_kernel(const float* __restrict__ x, const float* __restrict__ gamma_p,
                  float* __restrict__ out) {
    extern __shared__ char smem[];
    __nv_bfloat16* sQ  = (__nv_bfloat16*)smem;           // [BM][QSTR]  (34,816 B)
    char* stage_base   = smem + BM * QSTR * 2;           // 2 x STAGE_B
    float* sO = (float*)smem;                            // epilogue union

    const int b   = blockIdx.y;
    const int n0  = blockIdx.x * BM;
    const int tid = threadIdx.x;
    const int wid = tid >> 5;
    const int lane = tid & 31;

    const __nv_bfloat16* gK = g_k + (size_t)b * Nn * Cn;
    const __nv_bfloat16* gV = g_v + (size_t)b * Nn * Cn;
    const float* xb = x + (size_t)b * Cn * Nn + n0;

    // ======== prologue: Q = proj(x tile) computed in-CTA ========
    __nv_bfloat16* xs = (__nv_bfloat16*)stage_base;            // stage0 region
    __nv_bfloat16* ws = (__nv_bfloat16*)(stage_base + STAGE_B); // stage1 region

    // w_q via cp.async
#pragma unroll
    for (int i = 0; i < 16; i++) {
        int idx = tid + i * 128;
        int o  = idx >> 4;
        int c8 = (idx & 15) * 8;
        cp_async16(smem_u32(ws + o * KSTR + c8), g_w2 + (size_t)o * Cn + c8);
    }
    cp_commit();
    // x fp32 -> bf16 [k][n]
#pragma unroll
    for (int i = 0; i < 32; i++) {
        int idx = tid + i * 128;
        int row = idx >> 5;
        int n4  = (idx & 31) * 4;
        float4 v = *(const float4*)(xb + (size_t)row * Nn + n4);
        *(uint2*)&xs[row * KSTR + n4] = make_uint2(pack_bf16(v.x, v.y), pack_bf16(v.z, v.w));
    }
    cp_wait<0>();
    __syncthreads();

    const int g = lane >> 2, t = lane & 3;
    const int b_row = ((lane >> 4) & 1) * 8 + (lane & 7);
    const int b_col = ((lane >> 3) & 1) * 8;

    float o_acc[2][16][4];   // doubles as Q-GEMM accumulator in prologue
#pragma unroll
    for (int h = 0; h < 2; h++)
#pragma unroll
        for (int i = 0; i < 16; i++)
#pragma unroll
            for (int j = 0; j < 4; j++) o_acc[h][i][j] = 0.f;

    {
        const uint32_t xsa = smem_u32(xs);
        const uint32_t wsa = smem_u32(ws);
        const int a_krow = ((lane >> 4) & 1) * 8 + (lane & 7);
        const int a_ncol = ((lane >> 3) & 1) * 8;
        const uint32_t qa0 = xsa + (uint32_t)(a_krow * KSTR + wid * 32 + a_ncol) * 2;
        const uint32_t qa1 = qa0 + 16 * 2;
#pragma unroll
        for (int ki = 0; ki < 8; ki++) {
            uint32_t a00, a01, a02, a03, a10, a11, a12, a13;
            ldsm_x4_t(a00, a01, a02, a03, qa0 + (uint32_t)(ki * 16 * KSTR) * 2);
            ldsm_x4_t(a10, a11, a12, a13, qa1 + (uint32_t)(ki * 16 * KSTR) * 2);
#pragma unroll
            for (int j = 0; j < 16; j += 2) {
                uint32_t b0, b1, b2, b3;
                uint32_t ba = wsa + (uint32_t)(((j * 8) + b_row) * KSTR + ki * 16 + b_col) * 2;
                ldsm_x4(b0, b1, b2, b3, ba);
                mma16816(o_acc[0][j],     a00, a01, a02, a03, b0, b1);
                mma16816(o_acc[0][j + 1], a00, a01, a02, a03, b2, b3);
                mma16816(o_acc[1][j],     a10, a11, a12, a13, b0, b1);
                mma16816(o_acc[1][j + 1], a10, a11, a12, a13, b2, b3);
            }
        }
    }
    __syncthreads();   // xs/ws fully consumed; stage buffers free

    // KV tile 0 into stage0 (overlaps sQ writes below)
    {
        __nv_bfloat16* dK = (__nv_bfloat16*)stage_base;
        __nv_bfloat16* dV = dK + BN * QSTR;
#pragma unroll
        for (int i = 0; i < 8; i++) {
            int idx = tid + i * 128;
            int r = idx >> 4;
            int c = (idx & 15) * 8;
            cp_async16(smem_u32(dK + r * QSTR + c), gK + (size_t)r * Cn + c);
            cp_async16(smem_u32(dV + r * QSTR + c), gV + (size_t)r * Cn + c);
        }
        cp_commit();
    }

    // write Q (bf16) into sQ, then reset accumulators
#pragma unroll
    for (int h = 0; h < 2; h++) {
        const int r0 = wid * 32 + h * 16 + g;
#pragma unroll
        for (int j = 0; j < 16; j++) {
            int col = j * 8 + t * 2;
            *(uint32_t*)&sQ[r0 * QSTR + col]       = pack_bf16(o_acc[h][j][0], o_acc[h][j][1]);
            *(uint32_t*)&sQ[(r0 + 8) * QSTR + col] = pack_bf16(o_acc[h][j][2], o_acc[h][j][3]);
        }
    }
#pragma unroll
    for (int h = 0; h < 2; h++)
#pragma unroll
        for (int i = 0; i < 16; i++)
#pragma unroll
            for (int j = 0; j < 4; j++) o_acc[h][i][j] = 0.f;

    float lA[2] = {0.f, 0.f}, lB[2] = {0.f, 0.f};

    const uint32_t sQa   = smem_u32(sQ);
    const uint32_t sKV0a = smem_u32(stage_base);

    const int q_sub = ((lane >> 3) & 1) * 8 + (lane & 7);
    const uint32_t a_base0 = sQa + (uint32_t)((wid * 32 + q_sub) * QSTR + (lane >> 4) * 8) * 2;
    const uint32_t a_base1 = a_base0 + (uint32_t)(16 * QSTR) * 2;
    const int k4_rowoff = ((lane >> 4) & 1) * 8 + (lane & 7);
    const int k4_col    = ((lane >> 3) & 1) * 8;
    const int v4_row    = ((lane >> 3) & 1) * 8 + (lane & 7);
    const int v4_csel   = (lane >> 4) & 1;

    constexpr int T = Nn / BN;
    for (int it = 0; it < T; it++) {
        const int cur = it & 1;
        cp_wait<0>();
        __syncthreads();

        if (it + 1 < T) {
            __nv_bfloat16* dK = (__nv_bfloat16*)(stage_base + ((it + 1) & 1) * STAGE_B);
            __nv_bfloat16* dV = dK + BN * QSTR;
            const __nv_bfloat16* sgK = gK + (size_t)(it + 1) * BN * Cn;
            const __nv_bfloat16* sgV = gV + (size_t)(it + 1) * BN * Cn;
#pragma unroll
            for (int i = 0; i < 8; i++) {
                int idx = tid + i * 128;
                int r = idx >> 4;
                int c = (idx & 15) * 8;
                cp_async16(smem_u32(dK + r * QSTR + c), sgK + (size_t)r * Cn + c);
                cp_async16(smem_u32(dV + r * QSTR + c), sgV + (size_t)r * Cn + c);
            }
            cp_commit();
        }

        const uint32_t sKa = sKV0a + (uint32_t)(cur * STAGE_B);
        const uint32_t sVa = sKa + (uint32_t)(BN * QSTR) * 2;

        // ---- S = Q @ K^T : 32 x 64 per warp ----
        float s[2][8][4];
#pragma unroll
        for (int h = 0; h < 2; h++)
#pragma unroll
            for (int j = 0; j < 8; j++)
#pragma unroll
                for (int q = 0; q < 4; q++) s[h][j][q] = 0.f;

#pragma unroll
        for (int ki = 0; ki < 8; ki++) {
            uint32_t a00, a01, a02, a03, a10, a11, a12, a13;
            ldsm_x4(a00, a01, a02, a03, a_base0 + ki * 32);
            ldsm_x4(a10, a11, a12, a13, a_base1 + ki * 32);
#pragma unroll
            for (int j = 0; j < 8; j += 2) {
                uint32_t b0, b1, b2, b3;
                uint32_t ka = sKa +
                    (uint32_t)((j * 8 + k4_rowoff) * QSTR + ki * 16 + k4_col) * 2;
                ldsm_x4(b0, b1, b2, b3, ka);
                mma16816(s[0][j],     a00, a01, a02, a03, b0, b1);
                mma16816(s[0][j + 1], a00, a01, a02, a03, b2, b3);
                mma16816(s[1][j],     a10, a11, a12, a13, b0, b1);
                mma16816(s[1][j + 1], a10, a11, a12, a13, b2, b3);
            }
        }

        // ---- softmax chunk + PV chunk interleaved (MUFU hides under HMMA) ----
#pragma unroll
        for (int s4 = 0; s4 < 4; s4++) {
            uint32_t pa[2][4];
#pragma unroll
            for (int h = 0; h < 2; h++) {
                float e0 = exp2f(s[h][2 * s4][0]);
                float e1 = exp2f(s[h][2 * s4][1]);
                float e2 = exp2f(s[h][2 * s4][2]);
                float e3 = exp2f(s[h][2 * s4][3]);
                float e4 = exp2f(s[h][2 * s4 + 1][0]);
                float e5 = exp2f(s[h][2 * s4 + 1][1]);
                float e6 = exp2f(s[h][2 * s4 + 1][2]);
                float e7 = exp2f(s[h][2 * s4 + 1][3]);
                lA[h] += e0 + e1 + e4 + e5;
                lB[h] += e2 + e3 + e6 + e7;
                pa[h][0] = pack_bf16(e0, e1);
                pa[h][1] = pack_bf16(e2, e3);
                pa[h][2] = pack_bf16(e4, e5);
                pa[h][3] = pack_bf16(e6, e7);
            }
            uint32_t vrow = (uint32_t)(s4 * 16 + v4_row) * QSTR;
#pragma unroll
            for (int cI = 0; cI < 16; cI += 2) {
                uint32_t b0, b1, b2, b3;
                ldsm_x4_t(b0, b1, b2, b3, sVa + (vrow + (cI + v4_csel) * 8) * 2);
                mma16816(o_acc[0][cI],     pa[0][0], pa[0][1], pa[0][2], pa[0][3], b0, b1);
                mma16816(o_acc[0][cI + 1], pa[0][0], pa[0][1], pa[0][2], pa[0][3], b2, b3);
                mma16816(o_acc[1][cI],     pa[1][0], pa[1][1], pa[1][2], pa[1][3], b0, b1);
                mma16816(o_acc[1][cI + 1], pa[1][0], pa[1][1], pa[1][2], pa[1][3], b2, b3);
            }
        }
    }

    // ---- reduce l across quads, fold gamma, fused epilogue ----
    const float gm = __ldg(gamma_p);
    float il0[2], il1[2];
#pragma unroll
    for (int h = 0; h < 2; h++) {
        float a = lA[h], bb = lB[h];
        a += __shfl_xor_sync(0xffffffffu, a, 1);
        a += __shfl_xor_sync(0xffffffffu, a, 2);
        bb += __shfl_xor_sync(0xffffffffu, bb, 1);
        bb += __shfl_xor_sync(0xffffffffu, bb, 2);
        il0[h] = gm / a;
        il1[h] = gm / bb;
    }
    __syncthreads();   // all warps done with smem tiles before sO overwrites
#pragma unroll
    for (int h = 0; h < 2; h++) {
        const int r0 = wid * 32 + h * 16 + g;
#pragma unroll
        for (int cI = 0; cI < 16; cI++) {
            int col = cI * 8 + t * 2;
            sO[r0 * SOSTR + col]           = o_acc[h][cI][0] * il0[h];
            sO[r0 * SOSTR + col + 1]       = o_acc[h][cI][1] * il0[h];
            sO[(r0 + 8) * SOSTR + col]     = o_acc[h][cI][2] * il1[h];
            sO[(r0 + 8) * SOSTR + col + 1] = o_acc[h][cI][3] * il1[h];
        }
    }
    __syncthreads();
    float* ob = out + (size_t)b * Cn * Nn + n0;
#pragma unroll
    for (int i = 0; i < 128; i++) {
        int idx = tid + i * 128;
        int c    = idx >> 7;
        int mrow = idx & 127;
        ob[(size_t)c * Nn + mrow] = sO[mrow * SOSTR + c] + xb[(size_t)c * Nn + mrow];
    }
}

// ---------------- launch ----------------
extern "C" void kernel_launch(void* const* d_in, const int* in_sizes, int n_in,
                              void* d_out, int out_size) {
    const float* x   = (const float*)d_in[0];
    const float* dwq = (const float*)d_in[1];
    const float* pwq = (const float*)d_in[2];
    const float* dwk = (const float*)d_in[3];
    const float* pwk = (const float*)d_in[4];
    const float* dwv = (const float*)d_in[5];
    const float* pwv = (const float*)d_in[6];
    const float* gm  = (const float*)d_in[7];
    float* out = (float*)d_out;

    const int proj_smem  = 3 * Cn * KSTR * (int)sizeof(__nv_bfloat16);                 // 104,448 B
    const int flash_smem = (BM * QSTR + 4 * BN * QSTR) * (int)sizeof(__nv_bfloat16);   // 104,448 B

    cudaFuncSetAttribute(proj_kernel,  cudaFuncAttributeMaxDynamicSharedMemorySize, proj_smem);
    cudaFuncSetAttribute(flash_kernel, cudaFuncAttributeMaxDynamicSharedMemorySize, flash_smem);

    prep_weights_kernel<<<(3 * Cn * Cn + 255) / 256, 256>>>(pwq, dwq, pwk, dwk, pwv, dwv);
    proj_kernel<<<dim3(Nn / 128, Bn), 256, proj_smem>>>(x);
    flash_kernel<<<dim3(Nn / BM, Bn), 128, flash_smem>>>(x, gm, out);
}

// round 13
// speedup vs baseline: 1.4301x; 1.0122x over previous
#include <cuda_runtime.h>
#include <cuda_bf16.h>
#include <stdint.h>

#define DINL static __device__ __forceinline__

namespace {
constexpr int Bn = 8;
constexpr int Cn = 128;
constexpr int Nn = 4096;
constexpr int BM = 128;    // query rows per CTA
constexpr int BN = 64;     // keys per iteration
constexpr int QSTR = 136;  // bf16 smem row stride (conflict-free for ldmatrix)
constexpr int SOSTR = 133; // fp32 epilogue smem stride
constexpr int KSTR = 136;  // proj smem stride
constexpr int STAGE_B = 2 * BN * QSTR * 2;  // one KV stage in bytes (34,816)
}

// -------- scratch (no allocations allowed) --------
__device__ __align__(128) __nv_bfloat16 g_k[(size_t)Bn * Nn * Cn];  // k' = M x   [b][n][d]
__device__ __align__(128) __nv_bfloat16 g_v[(size_t)Bn * Nn * Cn];  // v          [b][n][d]
__device__ __align__(128) __nv_bfloat16 g_M[Cn * Cn];    // [a][b] = log2e*dwq[a]dwk[b]*sum_o pwq[o][a]pwk[o][b]
__device__ __align__(128) __nv_bfloat16 g_wv[Cn * Cn];   // [o][k] = pwv[o][k]*dwv[k]

// ---------------- PTX helpers ----------------
DINL uint32_t smem_u32(const void* p) { return (uint32_t)__cvta_generic_to_shared(p); }

DINL void ldsm_x4(uint32_t& r0, uint32_t& r1, uint32_t& r2, uint32_t& r3, uint32_t a) {
    asm volatile("ldmatrix.sync.aligned.m8n8.x4.shared.b16 {%0,%1,%2,%3}, [%4];"
                 : "=r"(r0), "=r"(r1), "=r"(r2), "=r"(r3) : "r"(a));
}
DINL void ldsm_x4_t(uint32_t& r0, uint32_t& r1, uint32_t& r2, uint32_t& r3, uint32_t a) {
    asm volatile("ldmatrix.sync.aligned.m8n8.x4.trans.shared.b16 {%0,%1,%2,%3}, [%4];"
                 : "=r"(r0), "=r"(r1), "=r"(r2), "=r"(r3) : "r"(a));
}
DINL void mma16816(float* c, uint32_t a0, uint32_t a1, uint32_t a2, uint32_t a3,
                   uint32_t b0, uint32_t b1) {
    asm volatile("mma.sync.aligned.m16n8k16.row.col.f32.bf16.bf16.f32 "
                 "{%0,%1,%2,%3}, {%4,%5,%6,%7}, {%8,%9}, {%0,%1,%2,%3};"
                 : "+f"(c[0]), "+f"(c[1]), "+f"(c[2]), "+f"(c[3])
                 : "r"(a0), "r"(a1), "r"(a2), "r"(a3), "r"(b0), "r"(b1));
}
DINL uint32_t pack_bf16(float lo, float hi) {
    uint32_t r;
    asm("cvt.rn.bf16x2.f32 %0, %1, %2;" : "=r"(r) : "f"(hi), "f"(lo));
    return r;
}
DINL void cp_async16(uint32_t saddr, const void* gptr) {
    asm volatile("cp.async.cg.shared.global [%0], [%1], 16;" :: "r"(saddr), "l"(gptr));
}
DINL void cp_commit() { asm volatile("cp.async.commit_group;"); }
template <int N> DINL void cp_wait() { asm volatile("cp.async.wait_group %0;" :: "n"(N)); }

// ---------------- kernel 1: prep  (blocks 0-63: M;  blocks 64-127: wv fold) ------
__global__ void prep_kernel(const float* __restrict__ pwq, const float* __restrict__ dwq,
                            const float* __restrict__ pwk, const float* __restrict__ dwk,
                            const float* __restrict__ pwv, const float* __restrict__ dwv) {
    const int blk = blockIdx.x;
    if (blk < 64) {
        int idx = blk * 256 + threadIdx.x;       // 0..16383
        int a = idx >> 7, bcol = idx & 127;
        float acc = 0.f;
#pragma unroll 8
        for (int o = 0; o < Cn; o++)
            acc = fmaf(pwq[o * Cn + a], pwk[o * Cn + bcol], acc);
        g_M[idx] = __float2bfloat16(acc * dwq[a] * dwk[bcol] * 1.4426950408889634f);
    } else {
        int idx = (blk - 64) * 256 + threadIdx.x;
        int k = idx & 127;
        g_wv[idx] = __float2bfloat16(pwv[idx] * dwv[k]);
    }
}

// ---------------- kernel 2: k'/v projections (double-buffered weights) ----------
__global__ __launch_bounds__(256, 2)
void proj_kernel(const float* __restrict__ x) {
    extern __shared__ char smraw[];
    __nv_bfloat16* xs  = (__nv_bfloat16*)smraw;      // [128 k][KSTR]
    __nv_bfloat16* ws0 = xs + Cn * KSTR;             // M  (for k')
    __nv_bfloat16* ws1 = ws0 + Cn * KSTR;            // w_v
    const int b   = blockIdx.y;
    const int n0  = blockIdx.x * 128;
    const int tid = threadIdx.x;
    const int wid = tid >> 5;
    const int lane = tid & 31;

#pragma unroll
    for (int i = 0; i < 8; i++) {
        int idx = tid + i * 256;
        int o  = idx >> 4;
        int c8 = (idx & 15) * 8;
        cp_async16(smem_u32(ws0 + o * KSTR + c8), g_M + (size_t)o * Cn + c8);
    }
    cp_commit();
#pragma unroll
    for (int i = 0; i < 8; i++) {
        int idx = tid + i * 256;
        int o  = idx >> 4;
        int c8 = (idx & 15) * 8;
        cp_async16(smem_u32(ws1 + o * KSTR + c8), g_wv + (size_t)o * Cn + c8);
    }
    cp_commit();

    const float* xb = x + (size_t)b * Cn * Nn + n0;
#pragma unroll
    for (int i = 0; i < 16; i++) {
        int idx = tid + i * 256;
        int row = idx >> 5;
        int n4  = (idx & 31) * 4;
        float4 v = *(const float4*)(xb + (size_t)row * Nn + n4);
        *(uint2*)&xs[row * KSTR + n4] = make_uint2(pack_bf16(v.x, v.y), pack_bf16(v.z, v.w));
    }

    const uint32_t xsa = smem_u32(xs);
    const int a_krow = ((lane >> 4) & 1) * 8 + (lane & 7);
    const int a_ncol = ((lane >> 3) & 1) * 8;
    const uint32_t a_base = xsa + (uint32_t)(a_krow * KSTR + wid * 16 + a_ncol) * 2;
    const int b_row = ((lane >> 4) & 1) * 8 + (lane & 7);
    const int b_col = ((lane >> 3) & 1) * 8;
    const int g = lane >> 2, t = lane & 3;
    const int r0 = wid * 16 + g;

    cp_wait<1>();
    __syncthreads();

#pragma unroll
    for (int p = 0; p < 2; p++) {
        if (p == 1) {
            cp_wait<0>();
            __syncthreads();
        }
        const uint32_t wsa = smem_u32(p == 0 ? ws0 : ws1);
        float acc[16][4];
#pragma unroll
        for (int i = 0; i < 16; i++)
#pragma unroll
            for (int j = 0; j < 4; j++) acc[i][j] = 0.f;
#pragma unroll
        for (int ki = 0; ki < 8; ki++) {
            uint32_t a0, a1, a2, a3;
            ldsm_x4_t(a0, a1, a2, a3, a_base + (uint32_t)(ki * 16 * KSTR) * 2);
#pragma unroll
            for (int j = 0; j < 16; j += 2) {
                uint32_t b0, b1, b2, b3;
                uint32_t ba = wsa +
                    (uint32_t)(((j * 8) + b_row) * KSTR + ki * 16 + b_col) * 2;
                ldsm_x4(b0, b1, b2, b3, ba);
                mma16816(acc[j],     a0, a1, a2, a3, b0, b1);
                mma16816(acc[j + 1], a0, a1, a2, a3, b2, b3);
            }
        }
        __nv_bfloat16* gout = (p == 0) ? g_k : g_v;
        __nv_bfloat16* obase = gout + ((size_t)b * Nn + n0) * Cn;
#pragma unroll
        for (int j = 0; j < 16; j++) {
            int col = j * 8 + t * 2;
            *(uint32_t*)(obase + (size_t)r0 * Cn + col)       = pack_bf16(acc[j][0], acc[j][1]);
            *(uint32_t*)(obase + (size_t)(r0 + 8) * Cn + col) = pack_bf16(acc[j][2], acc[j][3]);
        }
    }
}

// ---------------- kernel 3: flash attention (Q = x directly) --------------------
// grid (N/BM, B), 128 threads; warp w owns query rows [w*32, w*32+32)
__global__ __launch_bounds__(128, 2)
void flash_kernel(const float* __restrict__ x, const float* __restrict__ gamma_p,
                  float* __restrict__ out) {
    extern __shared__ char smem[];
    __nv_bfloat16* sQ  = (__nv_bfloat16*)smem;           // [128 d][QSTR]  (x tile, bf16, d-major)
    char* stage_base   = smem + BM * QSTR * 2;           // 2 x STAGE_B
    float* sO = (float*)smem;                            // epilogue union

    const int b   = blockIdx.y;
    const int n0  = blockIdx.x * BM;
    const int tid = threadIdx.x;
    const int wid = tid >> 5;
    const int lane = tid & 31;

    const __nv_bfloat16* gK = g_k + (size_t)b * Nn * Cn;
    const __nv_bfloat16* gV = g_v + (size_t)b * Nn * Cn;
    const float* xb = x + (size_t)b * Cn * Nn + n0;

    // KV tile 0 first (DRAM latency overlaps the x conversion below)
    {
        __nv_bfloat16* dK = (__nv_bfloat16*)stage_base;
        __nv_bfloat16* dV = dK + BN * QSTR;
#pragma unroll
        for (int i = 0; i < 8; i++) {
            int idx = tid + i * 128;
            int r = idx >> 4;
            int c = (idx & 15) * 8;
            cp_async16(smem_u32(dK + r * QSTR + c), gK + (size_t)r * Cn + c);
            cp_async16(smem_u32(dV + r * QSTR + c), gV + (size_t)r * Cn + c);
        }
        cp_commit();
    }

    // ---- prologue: sQ = bf16(x tile), kept in natural [d][n] layout ----
#pragma unroll
    for (int i = 0; i < 32; i++) {
        int idx = tid + i * 128;
        int row = idx >> 5;              // d
        int n4  = (idx & 31) * 4;        // n
        float4 v = *(const float4*)(xb + (size_t)row * Nn + n4);
        *(uint2*)&sQ[row * QSTR + n4] = make_uint2(pack_bf16(v.x, v.y), pack_bf16(v.z, v.w));
    }

    float o_acc[2][16][4];
#pragma unroll
    for (int h = 0; h < 2; h++)
#pragma unroll
        for (int i = 0; i < 16; i++)
#pragma unroll
            for (int j = 0; j < 4; j++) o_acc[h][i][j] = 0.f;

    float lA[2] = {0.f, 0.f}, lB[2] = {0.f, 0.f};

    const uint32_t sQa   = smem_u32(sQ);
    const uint32_t sKV0a = smem_u32(stage_base);

    // A fragments via ldmatrix.trans from [d][n] (proj-proven pattern)
    const int a_krow = ((lane >> 4) & 1) * 8 + (lane & 7);
    const int a_ncol = ((lane >> 3) & 1) * 8;
    const uint32_t a_base0 = sQa + (uint32_t)(a_krow * QSTR + wid * 32 + a_ncol) * 2;
    const uint32_t a_base1 = a_base0 + 16 * 2;
    const int k4_rowoff = ((lane >> 4) & 1) * 8 + (lane & 7);
    const int k4_col    = ((lane >> 3) & 1) * 8;
    const int v4_row    = ((lane >> 3) & 1) * 8 + (lane & 7);
    const int v4_csel   = (lane >> 4) & 1;
    const int g = lane >> 2, t = lane & 3;

    constexpr int T = Nn / BN;
    for (int it = 0; it < T; it++) {
        const int cur = it & 1;
        cp_wait<0>();
        __syncthreads();   // KV(it) + (it==0: sQ stores) visible; all warps past iter it-1

        if (it + 1 < T) {
            __nv_bfloat16* dK = (__nv_bfloat16*)(stage_base + ((it + 1) & 1) * STAGE_B);
            __nv_bfloat16* dV = dK + BN * QSTR;
            const __nv_bfloat16* sgK = gK + (size_t)(it + 1) * BN * Cn;
            const __nv_bfloat16* sgV = gV + (size_t)(it + 1) * BN * Cn;
#pragma unroll
            for (int i = 0; i < 8; i++) {
                int idx = tid + i * 128;
                int r = idx >> 4;
                int c = (idx & 15) * 8;
                cp_async16(smem_u32(dK + r * QSTR + c), sgK + (size_t)r * Cn + c);
                cp_async16(smem_u32(dV + r * QSTR + c), sgV + (size_t)r * Cn + c);
            }
            cp_commit();
        }

        const uint32_t sKa = sKV0a + (uint32_t)(cur * STAGE_B);
        const uint32_t sVa = sKa + (uint32_t)(BN * QSTR) * 2;

        // ---- S = X^T @ K'^T : 32 x 64 per warp ----
        float s[2][8][4];
#pragma unroll
        for (int h = 0; h < 2; h++)
#pragma unroll
            for (int j = 0; j < 8; j++)
#pragma unroll
                for (int q = 0; q < 4; q++) s[h][j][q] = 0.f;

#pragma unroll
        for (int ki = 0; ki < 8; ki++) {
            uint32_t a00, a01, a02, a03, a10, a11, a12, a13;
            ldsm_x4_t(a00, a01, a02, a03, a_base0 + (uint32_t)(ki * 16 * QSTR) * 2);
            ldsm_x4_t(a10, a11, a12, a13, a_base1 + (uint32_t)(ki * 16 * QSTR) * 2);
#pragma unroll
            for (int j = 0; j < 8; j += 2) {
                uint32_t b0, b1, b2, b3;
                uint32_t ka = sKa +
                    (uint32_t)((j * 8 + k4_rowoff) * QSTR + ki * 16 + k4_col) * 2;
                ldsm_x4(b0, b1, b2, b3, ka);
                mma16816(s[0][j],     a00, a01, a02, a03, b0, b1);
                mma16816(s[0][j + 1], a00, a01, a02, a03, b2, b3);
                mma16816(s[1][j],     a10, a11, a12, a13, b0, b1);
                mma16816(s[1][j + 1], a10, a11, a12, a13, b2, b3);
            }
        }

        // ---- softmax chunk + PV chunk interleaved (MUFU hides under HMMA) ----
#pragma unroll
        for (int s4 = 0; s4 < 4; s4++) {
            uint32_t pa[2][4];
#pragma unroll
            for (int h = 0; h < 2; h++) {
                float e0 = exp2f(s[h][2 * s4][0]);
                float e1 = exp2f(s[h][2 * s4][1]);
                float e2 = exp2f(s[h][2 * s4][2]);
                float e3 = exp2f(s[h][2 * s4][3]);
                float e4 = exp2f(s[h][2 * s4 + 1][0]);
                float e5 = exp2f(s[h][2 * s4 + 1][1]);
                float e6 = exp2f(s[h][2 * s4 + 1][2]);
                float e7 = exp2f(s[h][2 * s4 + 1][3]);
                lA[h] += e0 + e1 + e4 + e5;
                lB[h] += e2 + e3 + e6 + e7;
                pa[h][0] = pack_bf16(e0, e1);
                pa[h][1] = pack_bf16(e2, e3);
                pa[h][2] = pack_bf16(e4, e5);
                pa[h][3] = pack_bf16(e6, e7);
            }
            uint32_t vrow = (uint32_t)(s4 * 16 + v4_row) * QSTR;
#pragma unroll
            for (int cI = 0; cI < 16; cI += 2) {
                uint32_t b0, b1, b2, b3;
                ldsm_x4_t(b0, b1, b2, b3, sVa + (vrow + (cI + v4_csel) * 8) * 2);
                mma16816(o_acc[0][cI],     pa[0][0], pa[0][1], pa[0][2], pa[0][3], b0, b1);
                mma16816(o_acc[0][cI + 1], pa[0][0], pa[0][1], pa[0][2], pa[0][3], b2, b3);
                mma16816(o_acc[1][cI],     pa[1][0], pa[1][1], pa[1][2], pa[1][3], b0, b1);
                mma16816(o_acc[1][cI + 1], pa[1][0], pa[1][1], pa[1][2], pa[1][3], b2, b3);
            }
        }
    }

    // ---- reduce l across quads, fold gamma, fused epilogue ----
    const float gm = __ldg(gamma_p);
    float il0[2], il1[2];
#pragma unroll
    for (int h = 0; h < 2; h++) {
        float a = lA[h], bb = lB[h];
        a += __shfl_xor_sync(0xffffffffu, a, 1);
        a += __shfl_xor_sync(0xffffffffu, a, 2);
        bb += __shfl_xor_sync(0xffffffffu, bb, 1);
        bb += __shfl_xor_sync(0xffffffffu, bb, 2);
        il0[h] = gm / a;
        il1[h] = gm / bb;
    }
    __syncthreads();   // all warps done with smem tiles before sO overwrites
#pragma unroll
    for (int h = 0; h < 2; h++) {
        const int r0 = wid * 32 + h * 16 + g;
#pragma unroll
        for (int cI = 0; cI < 16; cI++) {
            int col = cI * 8 + t * 2;
            sO[r0 * SOSTR + col]           = o_acc[h][cI][0] * il0[h];
            sO[r0 * SOSTR + col + 1]       = o_acc[h][cI][1] * il0[h];
            sO[(r0 + 8) * SOSTR + col]     = o_acc[h][cI][2] * il1[h];
            sO[(r0 + 8) * SOSTR + col + 1] = o_acc[h][cI][3] * il1[h];
        }
    }
    __syncthreads();
    float* ob = out + (size_t)b * Cn * Nn + n0;
#pragma unroll
    for (int i = 0; i < 128; i++) {
        int idx = tid + i * 128;
        int c    = idx >> 7;
        int mrow = idx & 127;
        ob[(size_t)c * Nn + mrow] = sO[mrow * SOSTR + c] + xb[(size_t)c * Nn + mrow];
    }
}

// ---------------- launch ----------------
extern "C" void kernel_launch(void* const* d_in, const int* in_sizes, int n_in,
                              void* d_out, int out_size) {
    const float* x   = (const float*)d_in[0];
    const float* dwq = (const float*)d_in[1];
    const float* pwq = (const float*)d_in[2];
    const float* dwk = (const float*)d_in[3];
    const float* pwk = (const float*)d_in[4];
    const float* dwv = (const float*)d_in[5];
    const float* pwv = (const float*)d_in[6];
    const float* gm  = (const float*)d_in[7];
    float* out = (float*)d_out;

    const int proj_smem  = 3 * Cn * KSTR * (int)sizeof(__nv_bfloat16);                 // 104,448 B
    const int flash_smem = (BM * QSTR + 4 * BN * QSTR) * (int)sizeof(__nv_bfloat16);   // 104,448 B

    cudaFuncSetAttribute(proj_kernel,  cudaFuncAttributeMaxDynamicSharedMemorySize, proj_smem);
    cudaFuncSetAttribute(flash_kernel, cudaFuncAttributeMaxDynamicSharedMemorySize, flash_smem);

    prep_kernel<<<128, 256>>>(pwq, dwq, pwk, dwk, pwv, dwv);
    proj_kernel<<<dim3(Nn / 128, Bn), 256, proj_smem>>>(x);
    flash_kernel<<<dim3(Nn / BM, Bn), 128, flash_smem>>>(x, gm, out);
}